// round 2
// baseline (speedup 1.0000x reference)
#include <cuda_runtime.h>

// PixelShuffle / depth-to-space, R=2, feature-major grouping.
// in : [B=8, X=256, Y=256, C=256] fp32
// out: [B, 2X=512, 2Y=512, F=64]  fp32
// out[b, 2x+i, 2y+j, f] = in[b, x, y, 4f + 2i + j]
//
// 16 threads per input pixel. Thread t:
//   loads channels [16t, 16t+16) as 4x LDG.128.CS (coalesced; warp reads 2KB contig)
//   writes 4x STG.128.CS, one per output (i,j) row phase.
// Streaming cache hints: zero reuse, keep the 1 GiB out of L2's working set.
// All offsets fit in 32 bits (max float4 index ~16.8M), so index math is 32-bit.

static constexpr int X = 256;
static constexpr int Y = 256;
static constexpr int C = 256;   // = 64 features * 4
static constexpr int THREADS = 256;

__global__ void __launch_bounds__(THREADS, 8)
pixel_shuffle_kernel(const float4* __restrict__ in, float4* __restrict__ out) {
    const unsigned g = blockIdx.x * THREADS + threadIdx.x;

    const unsigned t = g & 15u;           // 16-channel chunk within pixel
    const unsigned p = g >> 4;            // input pixel id: b*65536 + x*256 + y

    const unsigned y = p & 255u;
    const unsigned x = (p >> 8) & 255u;
    const unsigned b = p >> 16;

    // ---- load: 16 contiguous channels = 4 float4, streaming ----
    const float4* ip = in + (size_t)p * (C / 4) + t * 4;
    const float4 v0 = __ldcs(ip + 0);
    const float4 v1 = __ldcs(ip + 1);
    const float4 v2 = __ldcs(ip + 2);
    const float4 v3 = __ldcs(ip + 3);

    // v{k}.c = channel 16t + 4k + c  (feature 4t+k, phase c = 2i + j)

    // ---- store: one float4 per (i,j) output row, streaming ----
    // out float4 index: base = ((b*512 + 2x)*512 + 2y)*16 + t
    const unsigned obase = (((b * (2 * X) + 2 * x) * (2 * Y)) + 2 * y) * 16 + t;
    const unsigned ROWI = (2 * Y) * 16;   // +i stride (one output X-row)
    const unsigned ROWJ = 16;             // +j stride (one output Y-row)

    __stcs(out + obase,               make_float4(v0.x, v1.x, v2.x, v3.x)); // i=0,j=0
    __stcs(out + obase + ROWJ,        make_float4(v0.y, v1.y, v2.y, v3.y)); // i=0,j=1
    __stcs(out + obase + ROWI,        make_float4(v0.z, v1.z, v2.z, v3.z)); // i=1,j=0
    __stcs(out + obase + ROWI + ROWJ, make_float4(v0.w, v1.w, v2.w, v3.w)); // i=1,j=1
}

extern "C" void kernel_launch(void* const* d_in, const int* in_sizes, int n_in,
                              void* d_out, int out_size) {
    (void)n_in; (void)out_size;
    const float4* in = (const float4*)d_in[0];
    float4* out = (float4*)d_out;

    const long long total_elems = (long long)in_sizes[0];   // B*X*Y*C
    const long long n_threads = total_elems / 16;           // 16 channels per thread
    const int grid = (int)((n_threads + THREADS - 1) / THREADS);

    pixel_shuffle_kernel<<<grid, THREADS>>>(in, out);
}

// round 4
// speedup vs baseline: 1.0308x; 1.0308x over previous
#include <cuda_runtime.h>

// PixelShuffle / depth-to-space, R=2, feature-major grouping.
// in : [B=8, X=256, Y=256, C=256] fp32
// out: [B, 2X=512, 2Y=512, F=64]  fp32
// out[b, 2x+i, 2y+j, f] = in[b, x, y, 4f + 2i + j]
//
// 16 threads per input pixel. Thread t:
//   loads channels [16t, 16t+16) as 4x LDG.128 (warp reads 2KB contiguous)
//   writes 4x STG.128, one per (i,j) phase. Per warp, each i-phase's stores
//   cover a 1KB contiguous run (16 threads x 2 j-phases x 2 pixels).
// Default cache ops: .cs streaming hints measured SLOWER (L1 replay churn,
// DRAM 86.3% -> 79.5%). All offsets fit in 32 bits.

static constexpr int X = 256;
static constexpr int Y = 256;
static constexpr int C = 256;   // = 64 features * 4
static constexpr int THREADS = 256;

__global__ void __launch_bounds__(THREADS, 8)
pixel_shuffle_kernel(const float4* __restrict__ in, float4* __restrict__ out) {
    const unsigned g = blockIdx.x * THREADS + threadIdx.x;

    const unsigned t = g & 15u;           // 16-channel chunk within pixel
    const unsigned p = g >> 4;            // input pixel id: b*65536 + x*256 + y

    const unsigned y = p & 255u;
    const unsigned x = (p >> 8) & 255u;
    const unsigned b = p >> 16;

    // ---- load: 16 contiguous channels = 4 float4 ----
    const float4* ip = in + (size_t)p * (C / 4) + t * 4;
    const float4 v0 = ip[0];
    const float4 v1 = ip[1];
    const float4 v2 = ip[2];
    const float4 v3 = ip[3];

    // v{k}.c = channel 16t + 4k + c  (feature 4t+k, phase c = 2i + j)

    // ---- store: one float4 per (i,j) output row ----
    // out float4 index: base = ((b*512 + 2x)*512 + 2y)*16 + t
    const unsigned obase = (((b * (2 * X) + 2 * x) * (2 * Y)) + 2 * y) * 16 + t;
    const unsigned ROWI = (2 * Y) * 16;   // +i stride (one output X-row)
    const unsigned ROWJ = 16;             // +j stride (one output Y-row)

    out[obase]               = make_float4(v0.x, v1.x, v2.x, v3.x); // i=0,j=0
    out[obase + ROWJ]        = make_float4(v0.y, v1.y, v2.y, v3.y); // i=0,j=1
    out[obase + ROWI]        = make_float4(v0.z, v1.z, v2.z, v3.z); // i=1,j=0
    out[obase + ROWI + ROWJ] = make_float4(v0.w, v1.w, v2.w, v3.w); // i=1,j=1
}

extern "C" void kernel_launch(void* const* d_in, const int* in_sizes, int n_in,
                              void* d_out, int out_size) {
    (void)n_in; (void)out_size;
    const float4* in = (const float4*)d_in[0];
    float4* out = (float4*)d_out;

    const long long total_elems = (long long)in_sizes[0];   // B*X*Y*C
    const long long n_threads = total_elems / 16;           // 16 channels per thread
    const int grid = (int)((n_threads + THREADS - 1) / THREADS);

    pixel_shuffle_kernel<<<grid, THREADS>>>(in, out);
}